// round 6
// baseline (speedup 1.0000x reference)
#include <cuda_runtime.h>
#include <cuda_bf16.h>

#define NB 16
#define NP 65536
#define NT 48
#define THRESH 0.35f
#define PUSH_T 0.2f

// ---------------- scratch (no allocation allowed) ----------------
__device__ unsigned long long g_bestprior[NB * NT];
__device__ float  g_ce[NB * NP];          // loss_rank (pos -> 0), all >= 0
__device__ double g_loss_l;
__device__ double g_loss_lm;
__device__ double g_cepos[NB];
__device__ double g_topk[NB];
__device__ int    g_numpos[NB];
__device__ int    g_nposland;

// ---------------- shared math (MUST be identical between match & fixup) ----
__device__ __forceinline__ float sl1(float d) {
    d = fabsf(d);
    return d < 1.f ? 0.5f * d * d : d - 0.5f;
}

struct PF { float x1, y1, x2, y2, area; };

__device__ __forceinline__ PF pointform(float4 pr) {
    PF r;
    r.x1 = pr.x - 0.5f * pr.z; r.y1 = pr.y - 0.5f * pr.w;
    r.x2 = pr.x + 0.5f * pr.z; r.y2 = pr.y + 0.5f * pr.w;
    r.area = (r.x2 - r.x1) * (r.y2 - r.y1);
    return r;
}

__device__ __forceinline__ float ioup(const PF& p, float4 b, float barea) {
    float w = fminf(p.x2, b.z) - fmaxf(p.x1, b.x);
    float h = fminf(p.y2, b.w) - fmaxf(p.y1, b.y);
    w = fmaxf(w, 0.f); h = fmaxf(h, 0.f);
    float inter = w * h;
    return __fdividef(inter, p.area + barea - inter);  // inter==0 -> 0
}

__device__ __forceinline__ float calc_ll(const float* tg, float4 pr, float4 ld) {
    float inz = __fdividef(1.f, 0.1f * pr.z);
    float inw = __fdividef(1.f, 0.1f * pr.w);
    float t0 = ((tg[0] + tg[2]) * 0.5f - pr.x) * inz;
    float t1 = ((tg[1] + tg[3]) * 0.5f - pr.y) * inw;
    float t2 = __logf(__fdividef(tg[2] - tg[0], pr.z)) * 5.0f;
    float t3 = __logf(__fdividef(tg[3] - tg[1], pr.w)) * 5.0f;
    return sl1(ld.x - t0) + sl1(ld.y - t1) + sl1(ld.z - t2) + sl1(ld.w - t3);
}

__device__ __forceinline__ float calc_lm(const float* tg, float4 pr, const float2* lp) {
    float inz = __fdividef(1.f, 0.1f * pr.z);
    float inw = __fdividef(1.f, 0.1f * pr.w);
    float s = 0.f;
#pragma unroll
    for (int i = 0; i < 5; i++) {
        float2 d = lp[i];
        s += sl1(d.x - (tg[4 + 2 * i] - pr.x) * inz);
        s += sl1(d.y - (tg[5 + 2 * i] - pr.y) * inw);
    }
    return s;
}

__device__ __forceinline__ float calc_ce(float2 c, int cls) {
    float m = fmaxf(c.x, c.y);
    float ce = m + __logf(1.f + __expf(-fabsf(c.x - c.y))) - (cls ? c.y : c.x);
    return fmaxf(ce, 0.f);
}

// ---------------- kernel 0: init ----------------
__global__ void init_kernel() {
    int i = threadIdx.x;
    if (i == 0) { g_loss_l = 0.0; g_loss_lm = 0.0; g_nposland = 0; }
    if (i < NB) { g_cepos[i] = 0.0; g_topk[i] = 0.0; g_numpos[i] = 0; }
    for (int j = i; j < NB * NT; j += blockDim.x)
        g_bestprior[j] = 0xFFFFFFFFull;   // pack(iou=0, p=0)
}

// ---------------- kernel 1: fused match + loss ----------------
// grid (NP/512, NB), 256 threads; each thread handles priors p0 and p0+256.
__global__ void __launch_bounds__(256) match_loss_kernel(
    const float4* __restrict__ loc,
    const float2* __restrict__ conf,
    const float2* __restrict__ landm,
    const float4* __restrict__ priors,
    const float*  __restrict__ targets)
{
    __shared__ float  s_tg[NT * 15];
    __shared__ float4 s_box[NT];
    __shared__ float  s_area[NT];
    __shared__ unsigned long long s_best[NT];

    const int n = blockIdx.y;
    const int tid = threadIdx.x;

    for (int j = tid; j < NT * 15; j += 256)
        s_tg[j] = targets[n * NT * 15 + j];
    __syncthreads();
    if (tid < NT) {
        float4 b = make_float4(s_tg[tid * 15 + 0], s_tg[tid * 15 + 1],
                               s_tg[tid * 15 + 2], s_tg[tid * 15 + 3]);
        s_box[tid] = b;
        s_area[tid] = (b.z - b.x) * (b.w - b.y);
        s_best[tid] = 0xFFFFFFFFull;
    }
    __syncthreads();

    const int p0 = blockIdx.x * 512 + tid;
    const int p1 = p0 + 256;
    PF A = pointform(priors[p0]);
    PF B = pointform(priors[p1]);

    float bo0 = -1.f, bo1 = -1.f;
    int bt0 = 0, bt1 = 0;
    const unsigned lo0 = 0xFFFFFFFFu - (unsigned)p0;
    const unsigned lo1 = 0xFFFFFFFFu - (unsigned)p1;

#pragma unroll 4
    for (int t = 0; t < NT; t++) {
        float4 b = s_box[t];
        float at = s_area[t];
        float i0 = ioup(A, b, at);
        float i1 = ioup(B, b, at);
        if (i0 > bo0) { bo0 = i0; bt0 = t; }
        if (i1 > bo1) { bo1 = i1; bt1 = t; }
        if (i0 > PUSH_T) {
            unsigned long long c = ((unsigned long long)__float_as_uint(i0) << 32) | lo0;
            if (c > s_best[t]) atomicMax(&s_best[t], c);
        }
        if (i1 > PUSH_T) {
            unsigned long long c = ((unsigned long long)__float_as_uint(i1) << 32) | lo1;
            if (c > s_best[t]) atomicMax(&s_best[t], c);
        }
    }

    // --- per-prior loss (pre-override; fixup corrects <=NT priors) ---
    float ll = 0.f, lm = 0.f, cep = 0.f;
    int dpos = 0, dland = 0;
#pragma unroll
    for (int i = 0; i < 2; i++) {
        const int p = i ? p1 : p0;
        const float bto = i ? bo1 : bo0;
        const int bti = i ? bt1 : bt0;
        const float* tg = &s_tg[bti * 15];
        const int conft = (bto >= THRESH) ? (int)tg[14] : 0;
        const bool pos = (conft != 0);
        const bool posland = (conft > 0);
        const int idx = n * NP + p;

        float2 c = conf[idx];
        float ce = calc_ce(c, pos ? 1 : 0);
        g_ce[idx] = pos ? 0.f : ce;

        if (pos) {
            cep += ce;
            dpos++;
            float4 pr = priors[p];
            ll += calc_ll(tg, pr, loc[idx]);
            if (posland) {
                dland++;
                lm += calc_lm(tg, pr, &landm[(size_t)idx * 5]);
            }
        }
    }

    // block reduce 5 quantities
    float a = ll, b2 = lm, cc = cep;
    int d = dpos, e = dland;
#pragma unroll
    for (int o = 16; o; o >>= 1) {
        a  += __shfl_down_sync(0xffffffffu, a, o);
        b2 += __shfl_down_sync(0xffffffffu, b2, o);
        cc += __shfl_down_sync(0xffffffffu, cc, o);
        d  += __shfl_down_sync(0xffffffffu, d, o);
        e  += __shfl_down_sync(0xffffffffu, e, o);
    }
    __shared__ float r_a[8], r_b[8], r_c[8];
    __shared__ int r_d[8], r_e[8];
    int wid = tid >> 5, lane = tid & 31;
    if (lane == 0) { r_a[wid] = a; r_b[wid] = b2; r_c[wid] = cc; r_d[wid] = d; r_e[wid] = e; }
    __syncthreads();
    if (tid == 0) {
        float A2 = 0, B3 = 0, C = 0; int D = 0, E = 0;
#pragma unroll
        for (int w = 0; w < 8; w++) { A2 += r_a[w]; B3 += r_b[w]; C += r_c[w]; D += r_d[w]; E += r_e[w]; }
        if (A2 != 0.f) atomicAdd(&g_loss_l, (double)A2);
        if (B3 != 0.f) atomicAdd(&g_loss_lm, (double)B3);
        if (C != 0.f) atomicAdd(&g_cepos[n], (double)C);
        if (D) atomicAdd(&g_numpos[n], D);
        if (E) atomicAdd(&g_nposland, E);
    }
}

// ---------------- kernel 2: fixup for overridden priors ----------------
// grid NB, 64 threads (t < NT active).
__global__ void fixup_kernel(
    const float4* __restrict__ loc,
    const float2* __restrict__ conf,
    const float2* __restrict__ landm,
    const float4* __restrict__ priors,
    const float*  __restrict__ targets)
{
    const int n = blockIdx.x;
    const int t = threadIdx.x;
    __shared__ float  s_tg[NT * 15];
    __shared__ float4 s_box[NT];
    __shared__ float  s_area[NT];
    __shared__ int    s_p[NT];
    __shared__ float  s_oldOv[NT];
    __shared__ int    s_oldT[NT];

    for (int j = t; j < NT * 15; j += 64)
        s_tg[j] = targets[n * NT * 15 + j];
    __syncthreads();
    if (t < NT) {
        float4 b = make_float4(s_tg[t * 15 + 0], s_tg[t * 15 + 1],
                               s_tg[t * 15 + 2], s_tg[t * 15 + 3]);
        s_box[t] = b;
        s_area[t] = (b.z - b.x) * (b.w - b.y);
    }
    __syncthreads();

    if (t < NT) {
        unsigned long long v = g_bestprior[n * NT + t];
        int p = (int)(0xFFFFFFFFu - (unsigned)(v & 0xFFFFFFFFull));
        if ((unsigned)(v >> 32) == 0u) {
            // no candidate above PUSH_T pushed: exact fallback row-argmax
            float4 bb = s_box[t]; float ba = s_area[t];
            float best = -1.f; int bp = 0;
            for (int q = 0; q < NP; q++) {
                PF pfq = pointform(priors[q]);
                float iou = ioup(pfq, bb, ba);
                if (iou > best) { best = iou; bp = q; }
            }
            p = bp;
        }
        s_p[t] = p;
        // recompute pre-override argmax at p (bit-identical to match)
        PF pf = pointform(priors[p]);
        float bo = -1.f; int bt = 0;
        for (int tt = 0; tt < NT; tt++) {
            float iou = ioup(pf, s_box[tt], s_area[tt]);
            if (iou > bo) { bo = iou; bt = tt; }
        }
        s_oldOv[t] = bo;
        s_oldT[t] = bt;
    }
    __syncthreads();

    if (t < NT) {
        int p = s_p[t];
        bool surv = true;                      // last-wins: only last t for this p applies
        for (int t2 = t + 1; t2 < NT; t2++)
            if (s_p[t2] == p) { surv = false; break; }
        if (surv) {
            const int idx = n * NP + p;
            const float oldOv = s_oldOv[t];
            const int oldT = s_oldT[t];
            const float* tgo = &s_tg[oldT * 15];
            const float* tgn = &s_tg[t * 15];
            const int conft_o = (oldOv >= THRESH) ? (int)tgo[14] : 0;
            const int conft_n = (int)tgn[14];   // bto = 2.0 >= THRESH
            const bool pos_o = conft_o != 0, pos_n = conft_n != 0;
            const bool pl_o = conft_o > 0,  pl_n = conft_n > 0;

            float4 pr = priors[p];
            float4 ld = loc[idx];
            const float2* lp = &landm[(size_t)idx * 5];
            float2 c = conf[idx];
            float ce1 = calc_ce(c, 1);
            float ce0 = calc_ce(c, 0);

            double dl = 0.0, dlm = 0.0;
            if (pos_n) dl += (double)calc_ll(tgn, pr, ld);
            if (pos_o) dl -= (double)calc_ll(tgo, pr, ld);
            if (pl_n) dlm += (double)calc_lm(tgn, pr, lp);
            if (pl_o) dlm -= (double)calc_lm(tgo, pr, lp);
            double dcep = (pos_n ? (double)ce1 : 0.0) - (pos_o ? (double)ce1 : 0.0);
            g_ce[idx] = pos_n ? 0.f : ce0;
            int dnp = (pos_n ? 1 : 0) - (pos_o ? 1 : 0);
            int dnl = (pl_n ? 1 : 0) - (pl_o ? 1 : 0);

            if (dl != 0.0)  atomicAdd(&g_loss_l, dl);
            if (dlm != 0.0) atomicAdd(&g_loss_lm, dlm);
            if (dcep != 0.0) atomicAdd(&g_cepos[n], dcep);
            if (dnp) atomicAdd(&g_numpos[n], dnp);
            if (dnl) atomicAdd(&g_nposland, dnl);
        }
    }
}

// ---------------- kernel 3: per-batch top-k sum via 3-pass radix select ----
// <<<NB, 1024>>>  warp-aggregated histograms (keys cluster into few bins!)
__global__ void topk_kernel() {
    const int n = blockIdx.x;
    const uint4* k4 = reinterpret_cast<const uint4*>(&g_ce[n * NP]);
    long long k = (long long)7 * (long long)g_numpos[n];
    if (k > NP - 1) k = NP - 1;

    __shared__ unsigned s_hist[2048];
    __shared__ unsigned s_chunk[64];
    __shared__ unsigned s_pf, s_msk;
    __shared__ long long s_kk;

    const int tid = threadIdx.x;
    const int lane = tid & 31;
    if (k <= 0) { if (tid == 0) g_topk[n] = 0.0; return; }
    if (tid == 0) { s_pf = 0u; s_msk = 0u; s_kk = k; }
    __syncthreads();

    const int shifts[3] = {21, 10, 0};
    const unsigned bmasks[3] = {0x7FFu, 0x7FFu, 0x3FFu};

    for (int pass = 0; pass < 3; pass++) {
        const int shift = shifts[pass];
        const unsigned bmask = bmasks[pass];
        s_hist[tid] = 0u; s_hist[tid + 1024] = 0u;
        __syncthreads();
        const unsigned pf = s_pf, msk = s_msk;

        for (int i = tid; i < NP / 4; i += 1024) {
            uint4 v = k4[i];
#pragma unroll
            for (int j = 0; j < 4; j++) {
                unsigned key = (j == 0) ? v.x : (j == 1) ? v.y : (j == 2) ? v.z : v.w;
                bool ok = ((key & msk) == pf);
                unsigned bal = __ballot_sync(0xffffffffu, ok);
                if (ok) {
                    unsigned bin = (key >> shift) & bmask;
                    unsigned m = __match_any_sync(bal, bin);
                    if (lane == __ffs(m) - 1)
                        atomicAdd(&s_hist[bin], __popc(m));
                }
            }
        }
        __syncthreads();

        if (tid < 64) {
            unsigned s = 0;
#pragma unroll
            for (int j = 0; j < 32; j++) s += s_hist[tid * 32 + j];
            s_chunk[tid] = s;
        }
        __syncthreads();
        if (tid == 0) {
            long long kk = s_kk, cum = 0;
            int c = 63;
            for (; c > 0; c--) {
                long long cnt = (long long)s_chunk[c];
                if (cum + cnt >= kk) break;
                cum += cnt;
            }
            int b = c * 32;
            for (int j = c * 32 + 31; j >= c * 32; j--) {
                long long cnt = (long long)s_hist[j];
                if (cum + cnt >= kk) { b = j; break; }
                cum += cnt;
            }
            s_pf = pf | ((unsigned)b << shift);
            s_msk = msk | (bmask << shift);
            s_kk = kk - cum;
        }
        __syncthreads();
    }

    const unsigned thr = s_pf;
    const float thrv = __uint_as_float(thr);
    double sgt = 0.0;
    long long cgt = 0;
    for (int i = tid; i < NP / 4; i += 1024) {
        uint4 v = k4[i];
        if (v.x > thr) { sgt += (double)__uint_as_float(v.x); cgt++; }
        if (v.y > thr) { sgt += (double)__uint_as_float(v.y); cgt++; }
        if (v.z > thr) { sgt += (double)__uint_as_float(v.z); cgt++; }
        if (v.w > thr) { sgt += (double)__uint_as_float(v.w); cgt++; }
    }
#pragma unroll
    for (int o = 16; o; o >>= 1) {
        sgt += __shfl_down_sync(0xffffffffu, sgt, o);
        cgt += __shfl_down_sync(0xffffffffu, cgt, o);
    }
    __shared__ double r_s[32];
    __shared__ long long r_c[32];
    if (lane == 0) { r_s[tid >> 5] = sgt; r_c[tid >> 5] = cgt; }
    __syncthreads();
    if (tid == 0) {
        double S = 0; long long C = 0;
        for (int w = 0; w < 32; w++) { S += r_s[w]; C += r_c[w]; }
        g_topk[n] = S + (double)(k - C) * (double)thrv;
    }
}

// ---------------- kernel 4: final combine ----------------
__global__ void final_kernel(float* __restrict__ out) {
    if (threadIdx.x == 0) {
        double lc = 0.0;
        long long np = 0;
        for (int n = 0; n < NB; n++) { lc += g_cepos[n] + g_topk[n]; np += g_numpos[n]; }
        double Nn = np < 1 ? 1.0 : (double)np;
        int npl = g_nposland;
        double N1 = npl < 1 ? 1.0 : (double)npl;
        out[0] = (float)(g_loss_l / Nn);
        out[1] = (float)(lc / Nn);
        out[2] = (float)(g_loss_lm / N1);
    }
}

extern "C" void kernel_launch(void* const* d_in, const int* in_sizes, int n_in,
                              void* d_out, int out_size) {
    const float4* loc     = (const float4*)d_in[0];   // (16,65536,4) f32
    const float2* conf    = (const float2*)d_in[1];   // (16,65536,2) f32
    const float2* landm   = (const float2*)d_in[2];   // (16,65536,10) f32
    const float4* priors  = (const float4*)d_in[3];   // (65536,4) f32
    const float*  targets = (const float*)d_in[4];    // (16,48,15) f32
    float* out = (float*)d_out;

    init_kernel<<<1, 256>>>();
    match_loss_kernel<<<dim3(NP / 512, NB), 256>>>(loc, conf, landm, priors, targets);
    fixup_kernel<<<NB, 64>>>(loc, conf, landm, priors, targets);
    topk_kernel<<<NB, 1024>>>();
    final_kernel<<<1, 32>>>(out);
}

// round 7
// speedup vs baseline: 47.5918x; 47.5918x over previous
#include <cuda_runtime.h>
#include <cuda_bf16.h>

#define NB 16
#define NP 65536
#define NT 48
#define THRESH 0.35f

// ---------------- scratch (no allocation allowed) ----------------
__device__ unsigned long long g_bestprior[NB * NT];
__device__ __align__(16) float g_ce[NB * NP];   // loss_rank (pos -> 0), all >= 0
__device__ unsigned g_hist[NB * 2048];
__device__ unsigned g_pf[NB];
__device__ unsigned g_msk[NB];
__device__ long long g_kk[NB];
__device__ long long g_k7[NB];
__device__ double g_sumgt[NB];
__device__ int    g_cntgt[NB];
__device__ double g_loss_l;
__device__ double g_loss_lm;
__device__ double g_cepos[NB];
__device__ int    g_numpos[NB];
__device__ int    g_nposland;

// ---------------- shared math (bit-identical between match & fixup) --------
__device__ __forceinline__ float sl1(float d) {
    d = fabsf(d);
    return d < 1.f ? 0.5f * d * d : d - 0.5f;
}

struct PF { float x1, y1, x2, y2, area; };

__device__ __forceinline__ PF pointform(float4 pr) {
    PF r;
    r.x1 = __fmaf_rn(-0.5f, pr.z, pr.x);
    r.y1 = __fmaf_rn(-0.5f, pr.w, pr.y);
    r.x2 = __fmaf_rn( 0.5f, pr.z, pr.x);
    r.y2 = __fmaf_rn( 0.5f, pr.w, pr.y);
    r.area = __fmul_rn(__fsub_rn(r.x2, r.x1), __fsub_rn(r.y2, r.y1));
    return r;
}

// intersection area + union denominator, all explicitly rounded (no FMA drift)
__device__ __forceinline__ void inter_den(const PF& p, float4 b, float ba,
                                          float& inter, float& den) {
    float w = fmaxf(__fsub_rn(fminf(p.x2, b.z), fmaxf(p.x1, b.x)), 0.f);
    float h = fmaxf(__fsub_rn(fminf(p.y2, b.w), fmaxf(p.y1, b.y)), 0.f);
    inter = __fmul_rn(w, h);
    den = __fsub_rn(__fadd_rn(p.area, ba), inter);
}

// fraction-argmax over truths for one prior (used identically in fixup)
__device__ __forceinline__ void row_argmax(const PF& pf, const float4* s_box,
                                           const float* s_area,
                                           float& bnum, float& bden, int& bt) {
    bnum = -1.f; bden = 1.f; bt = 0;
    for (int t = 0; t < NT; t++) {
        float inter, den;
        inter_den(pf, s_box[t], s_area[t], inter, den);
        if (__fmul_rn(inter, bden) > __fmul_rn(bnum, den)) {
            bnum = inter; bden = den; bt = t;
        }
    }
}

__device__ __forceinline__ float calc_ll(const float* tg, float4 pr, float4 ld) {
    float inz = __fdividef(1.f, 0.1f * pr.z);
    float inw = __fdividef(1.f, 0.1f * pr.w);
    float t0 = ((tg[0] + tg[2]) * 0.5f - pr.x) * inz;
    float t1 = ((tg[1] + tg[3]) * 0.5f - pr.y) * inw;
    float t2 = __logf(__fdividef(tg[2] - tg[0], pr.z)) * 5.0f;
    float t3 = __logf(__fdividef(tg[3] - tg[1], pr.w)) * 5.0f;
    return sl1(ld.x - t0) + sl1(ld.y - t1) + sl1(ld.z - t2) + sl1(ld.w - t3);
}

__device__ __forceinline__ float calc_lm(const float* tg, float4 pr, const float2* lp) {
    float inz = __fdividef(1.f, 0.1f * pr.z);
    float inw = __fdividef(1.f, 0.1f * pr.w);
    float s = 0.f;
#pragma unroll
    for (int i = 0; i < 5; i++) {
        float2 d = lp[i];
        s += sl1(d.x - (tg[4 + 2 * i] - pr.x) * inz);
        s += sl1(d.y - (tg[5 + 2 * i] - pr.y) * inw);
    }
    return s;
}

__device__ __forceinline__ float calc_ce(float2 c, int cls) {
    float m = fmaxf(c.x, c.y);
    float ce = m + __logf(1.f + __expf(-fabsf(c.x - c.y))) - (cls ? c.y : c.x);
    return fmaxf(ce, 0.f);
}

// ---------------- kernel 0: init ----------------
__global__ void init_kernel() {
    int i = threadIdx.x;
    if (i == 0) { g_loss_l = 0.0; g_loss_lm = 0.0; g_nposland = 0; }
    if (i < NB) {
        g_cepos[i] = 0.0; g_numpos[i] = 0;
        g_pf[i] = 0u; g_msk[i] = 0u; g_kk[i] = 0; g_k7[i] = 0;
        g_sumgt[i] = 0.0; g_cntgt[i] = 0;
    }
    for (int j = i; j < NB * NT; j += blockDim.x)
        g_bestprior[j] = 0xFFFFFFFFull;   // pack(iou=0, p=0)
    for (int j = i; j < NB * 2048; j += blockDim.x)
        g_hist[j] = 0u;
}

// ---------------- kernel 1: fused match + loss (4 priors / thread) --------
// grid (NP/1024, NB), 256 threads.
__global__ void __launch_bounds__(256) match_loss_kernel(
    const float4* __restrict__ loc,
    const float2* __restrict__ conf,
    const float2* __restrict__ landm,
    const float4* __restrict__ priors,
    const float*  __restrict__ targets)
{
    __shared__ float  s_tg[NT * 15];
    __shared__ float4 s_box[NT];
    __shared__ float  s_area[NT];
    __shared__ unsigned long long s_best[NT];

    const int n = blockIdx.y;
    const int tid = threadIdx.x;

    for (int j = tid; j < NT * 15; j += 256)
        s_tg[j] = targets[n * NT * 15 + j];
    __syncthreads();
    if (tid < NT) {
        float4 b = make_float4(s_tg[tid * 15 + 0], s_tg[tid * 15 + 1],
                               s_tg[tid * 15 + 2], s_tg[tid * 15 + 3]);
        s_box[tid] = b;
        s_area[tid] = __fmul_rn(__fsub_rn(b.z, b.x), __fsub_rn(b.w, b.y));
        s_best[tid] = 0xFFFFFFFFull;
    }
    __syncthreads();

    int p[4];
    PF pf[4];
    float bnum[4], bden[4];
    int bt[4];
#pragma unroll
    for (int i = 0; i < 4; i++) {
        p[i] = blockIdx.x * 1024 + tid + i * 256;
        pf[i] = pointform(priors[p[i]]);
        bnum[i] = -1.f; bden[i] = 1.f; bt[i] = 0;
    }

#pragma unroll 2
    for (int t = 0; t < NT; t++) {
        float4 b = s_box[t];
        float at = s_area[t];
        // stale-read of running column max (monotone; atomic decides exactly)
        float cur = __uint_as_float(((const unsigned*)&s_best[t])[1]);
        float inter[4], den[4];
#pragma unroll
        for (int i = 0; i < 4; i++) {
            inter_den(pf[i], b, at, inter[i], den[i]);
            if (__fmul_rn(inter[i], bden[i]) > __fmul_rn(bnum[i], den[i])) {
                bnum[i] = inter[i]; bden[i] = den[i]; bt[i] = t;
            }
        }
#pragma unroll
        for (int i = 0; i < 4; i++) {
            // candidate can win only if iou > cur (with safety margin)
            if (inter[i] > __fmul_rn(cur, den[i]) * 0.9999f) {
                float iou = __fdividef(inter[i], den[i]);
                unsigned long long cand =
                    ((unsigned long long)__float_as_uint(iou) << 32) |
                    (unsigned long long)(0xFFFFFFFFu - (unsigned)p[i]);
                atomicMax(&s_best[t], cand);
            }
        }
    }

    // --- per-prior loss (pre-override; fixup corrects <=NT priors) ---
    float ll = 0.f, lm = 0.f, cep = 0.f;
    int dpos = 0, dland = 0;
#pragma unroll
    for (int i = 0; i < 4; i++) {
        const float bto = __fdividef(bnum[i], bden[i]);
        const float* tg = &s_tg[bt[i] * 15];
        const int conft = (bto >= THRESH) ? (int)tg[14] : 0;
        const bool pos = (conft != 0);
        const bool posland = (conft > 0);
        const int idx = n * NP + p[i];

        float2 c = conf[idx];
        float ce = calc_ce(c, pos ? 1 : 0);
        g_ce[idx] = pos ? 0.f : ce;

        if (pos) {
            cep += ce;
            dpos++;
            float4 pr = priors[p[i]];
            ll += calc_ll(tg, pr, loc[idx]);
            if (posland) {
                dland++;
                lm += calc_lm(tg, pr, &landm[(size_t)idx * 5]);
            }
        }
    }

    // block reduce 5 quantities
    float a = ll, b2 = lm, cc = cep;
    int d = dpos, e = dland;
#pragma unroll
    for (int o = 16; o; o >>= 1) {
        a  += __shfl_down_sync(0xffffffffu, a, o);
        b2 += __shfl_down_sync(0xffffffffu, b2, o);
        cc += __shfl_down_sync(0xffffffffu, cc, o);
        d  += __shfl_down_sync(0xffffffffu, d, o);
        e  += __shfl_down_sync(0xffffffffu, e, o);
    }
    __shared__ float r_a[8], r_b[8], r_c[8];
    __shared__ int r_d[8], r_e[8];
    int wid = tid >> 5, lane = tid & 31;
    if (lane == 0) { r_a[wid] = a; r_b[wid] = b2; r_c[wid] = cc; r_d[wid] = d; r_e[wid] = e; }
    __syncthreads();
    if (tid == 0) {
        float A2 = 0, B3 = 0, C = 0; int D = 0, E = 0;
#pragma unroll
        for (int w = 0; w < 8; w++) { A2 += r_a[w]; B3 += r_b[w]; C += r_c[w]; D += r_d[w]; E += r_e[w]; }
        if (A2 != 0.f) atomicAdd(&g_loss_l, (double)A2);
        if (B3 != 0.f) atomicAdd(&g_loss_lm, (double)B3);
        if (C != 0.f) atomicAdd(&g_cepos[n], (double)C);
        if (D) atomicAdd(&g_numpos[n], D);
        if (E) atomicAdd(&g_nposland, E);
    }
    if (tid < NT)
        atomicMax(&g_bestprior[n * NT + tid], s_best[tid]);
}

// ---------------- kernel 2: fixup for overridden priors ----------------
// grid NB, 64 threads (t < NT active).
__global__ void fixup_kernel(
    const float4* __restrict__ loc,
    const float2* __restrict__ conf,
    const float2* __restrict__ landm,
    const float4* __restrict__ priors,
    const float*  __restrict__ targets)
{
    const int n = blockIdx.x;
    const int t = threadIdx.x;
    __shared__ float  s_tg[NT * 15];
    __shared__ float4 s_box[NT];
    __shared__ float  s_area[NT];
    __shared__ int    s_p[NT];
    __shared__ float  s_oldNum[NT], s_oldDen[NT];
    __shared__ int    s_oldT[NT];

    for (int j = t; j < NT * 15; j += 64)
        s_tg[j] = targets[n * NT * 15 + j];
    __syncthreads();
    if (t < NT) {
        float4 b = make_float4(s_tg[t * 15 + 0], s_tg[t * 15 + 1],
                               s_tg[t * 15 + 2], s_tg[t * 15 + 3]);
        s_box[t] = b;
        s_area[t] = __fmul_rn(__fsub_rn(b.z, b.x), __fsub_rn(b.w, b.y));
    }
    __syncthreads();

    if (t < NT) {
        unsigned long long v = g_bestprior[n * NT + t];
        int p = (int)(0xFFFFFFFFu - (unsigned)(v & 0xFFFFFFFFull));
        s_p[t] = p;
        // recompute pre-override argmax at p (bit-identical to match)
        PF pf = pointform(priors[p]);
        float bn, bd; int bt;
        row_argmax(pf, s_box, s_area, bn, bd, bt);
        s_oldNum[t] = bn; s_oldDen[t] = bd; s_oldT[t] = bt;
    }
    __syncthreads();

    if (t < NT) {
        int p = s_p[t];
        bool surv = true;                      // last-wins per prior
        for (int t2 = t + 1; t2 < NT; t2++)
            if (s_p[t2] == p) { surv = false; break; }
        if (surv) {
            const int idx = n * NP + p;
            const float oldOv = __fdividef(s_oldNum[t], s_oldDen[t]);
            const int oldT = s_oldT[t];
            const float* tgo = &s_tg[oldT * 15];
            const float* tgn = &s_tg[t * 15];
            const int conft_o = (oldOv >= THRESH) ? (int)tgo[14] : 0;
            const int conft_n = (int)tgn[14];   // bto = 2.0 >= THRESH
            const bool pos_o = conft_o != 0, pos_n = conft_n != 0;
            const bool pl_o = conft_o > 0,  pl_n = conft_n > 0;

            float4 pr = priors[p];
            float4 ld = loc[idx];
            const float2* lp = &landm[(size_t)idx * 5];
            float2 c = conf[idx];
            float ce1 = calc_ce(c, 1);
            float ce0 = calc_ce(c, 0);

            double dl = 0.0, dlm = 0.0;
            if (pos_n) dl += (double)calc_ll(tgn, pr, ld);
            if (pos_o) dl -= (double)calc_ll(tgo, pr, ld);
            if (pl_n) dlm += (double)calc_lm(tgn, pr, lp);
            if (pl_o) dlm -= (double)calc_lm(tgo, pr, lp);
            double dcep = (pos_n ? (double)ce1 : 0.0) - (pos_o ? (double)ce1 : 0.0);
            g_ce[idx] = pos_n ? 0.f : ce0;
            int dnp = (pos_n ? 1 : 0) - (pos_o ? 1 : 0);
            int dnl = (pl_n ? 1 : 0) - (pl_o ? 1 : 0);

            if (dl != 0.0)  atomicAdd(&g_loss_l, dl);
            if (dlm != 0.0) atomicAdd(&g_loss_lm, dlm);
            if (dcep != 0.0) atomicAdd(&g_cepos[n], dcep);
            if (dnp) atomicAdd(&g_numpos[n], dnp);
            if (dnl) atomicAdd(&g_nposland, dnl);
        }
    }
}

// ---------------- topk: multi-block radix select ----------------
// hist: grid (16, NB), 256 threads; each block covers 4096 keys.
__global__ void topk_hist(int shift, unsigned bmask) {
    const int n = blockIdx.y;
    __shared__ unsigned s_h[2048];
    for (int j = threadIdx.x; j < 2048; j += 256) s_h[j] = 0u;
    __syncthreads();
    const unsigned pf = g_pf[n], msk = g_msk[n];
    const uint4* k4 = reinterpret_cast<const uint4*>(&g_ce[n * NP]);
    const int base = blockIdx.x * 1024;
    const int lane = threadIdx.x & 31;

    for (int i = threadIdx.x; i < 1024; i += 256) {
        uint4 v = k4[base + i];
#pragma unroll
        for (int j = 0; j < 4; j++) {
            unsigned key = (j == 0) ? v.x : (j == 1) ? v.y : (j == 2) ? v.z : v.w;
            bool ok = ((key & msk) == pf);
            unsigned bal = __ballot_sync(0xffffffffu, ok);
            if (ok) {
                unsigned bin = (key >> shift) & bmask;
                unsigned m = __match_any_sync(bal, bin);
                if (lane == __ffs(m) - 1)
                    atomicAdd(&s_h[bin], __popc(m));
            }
        }
    }
    __syncthreads();
    for (int j = threadIdx.x; j < 2048; j += 256) {
        unsigned c = s_h[j];
        if (c) atomicAdd(&g_hist[n * 2048 + j], c);
    }
}

// pick: <<<NB, 256>>> — select bin, zero hist for next pass.
__global__ void topk_pick(int pass, int shift, unsigned bmask) {
    const int n = blockIdx.x;
    __shared__ unsigned s_h[2048];
    __shared__ unsigned s_chunk[64];
    const int nbins = (int)bmask + 1;
    for (int j = threadIdx.x; j < nbins; j += 256) {
        s_h[j] = g_hist[n * 2048 + j];
        g_hist[n * 2048 + j] = 0u;
    }
    __syncthreads();
    const int nchunk = nbins / 32;
    if (threadIdx.x < nchunk) {
        unsigned s = 0;
#pragma unroll 8
        for (int j = 0; j < 32; j++) s += s_h[threadIdx.x * 32 + j];
        s_chunk[threadIdx.x] = s;
    }
    __syncthreads();
    if (threadIdx.x == 0) {
        long long kk;
        if (pass == 0) {
            long long k = 7LL * (long long)g_numpos[n];
            if (k > NP - 1) k = NP - 1;
            g_k7[n] = k;
            kk = k;
        } else {
            kk = g_kk[n];
        }
        if (kk > 0) {
            long long cum = 0;
            int c = nchunk - 1;
            for (; c > 0; c--) {
                long long cnt = (long long)s_chunk[c];
                if (cum + cnt >= kk) break;
                cum += cnt;
            }
            int b = c * 32;
            for (int j = c * 32 + 31; j >= c * 32; j--) {
                long long cnt = (long long)s_h[j];
                if (cum + cnt >= kk) { b = j; break; }
                cum += cnt;
            }
            g_pf[n] |= ((unsigned)b) << shift;
            g_msk[n] |= bmask << shift;
            g_kk[n] = kk - cum;
        }
    }
}

// sum of values strictly above threshold: grid (16, NB), 256 threads.
__global__ void topk_sum() {
    const int n = blockIdx.y;
    if (g_k7[n] <= 0) return;
    const unsigned thr = g_pf[n];
    const uint4* k4 = reinterpret_cast<const uint4*>(&g_ce[n * NP]);
    const int base = blockIdx.x * 1024;
    double s = 0.0;
    int c = 0;
    for (int i = threadIdx.x; i < 1024; i += 256) {
        uint4 v = k4[base + i];
        if (v.x > thr) { s += (double)__uint_as_float(v.x); c++; }
        if (v.y > thr) { s += (double)__uint_as_float(v.y); c++; }
        if (v.z > thr) { s += (double)__uint_as_float(v.z); c++; }
        if (v.w > thr) { s += (double)__uint_as_float(v.w); c++; }
    }
#pragma unroll
    for (int o = 16; o; o >>= 1) {
        s += __shfl_down_sync(0xffffffffu, s, o);
        c += __shfl_down_sync(0xffffffffu, c, o);
    }
    __shared__ double r_s[8];
    __shared__ int r_c[8];
    int wid = threadIdx.x >> 5, lane = threadIdx.x & 31;
    if (lane == 0) { r_s[wid] = s; r_c[wid] = c; }
    __syncthreads();
    if (threadIdx.x == 0) {
        double S = 0; int C = 0;
#pragma unroll
        for (int w = 0; w < 8; w++) { S += r_s[w]; C += r_c[w]; }
        if (S != 0.0) atomicAdd(&g_sumgt[n], S);
        if (C) atomicAdd(&g_cntgt[n], C);
    }
}

// ---------------- final combine ----------------
__global__ void final_kernel(float* __restrict__ out) {
    if (threadIdx.x == 0) {
        double lc = 0.0;
        long long np = 0;
        for (int n = 0; n < NB; n++) {
            long long k = g_k7[n];
            double tk = 0.0;
            if (k > 0) {
                double thrv = (double)__uint_as_float(g_pf[n]);
                tk = g_sumgt[n] + (double)(k - (long long)g_cntgt[n]) * thrv;
            }
            lc += g_cepos[n] + tk;
            np += g_numpos[n];
        }
        double Nn = np < 1 ? 1.0 : (double)np;
        int npl = g_nposland;
        double N1 = npl < 1 ? 1.0 : (double)npl;
        out[0] = (float)(g_loss_l / Nn);
        out[1] = (float)(lc / Nn);
        out[2] = (float)(g_loss_lm / N1);
    }
}

extern "C" void kernel_launch(void* const* d_in, const int* in_sizes, int n_in,
                              void* d_out, int out_size) {
    const float4* loc     = (const float4*)d_in[0];   // (16,65536,4) f32
    const float2* conf    = (const float2*)d_in[1];   // (16,65536,2) f32
    const float2* landm   = (const float2*)d_in[2];   // (16,65536,10) f32
    const float4* priors  = (const float4*)d_in[3];   // (65536,4) f32
    const float*  targets = (const float*)d_in[4];    // (16,48,15) f32
    float* out = (float*)d_out;

    init_kernel<<<1, 256>>>();
    match_loss_kernel<<<dim3(NP / 1024, NB), 256>>>(loc, conf, landm, priors, targets);
    fixup_kernel<<<NB, 64>>>(loc, conf, landm, priors, targets);
    topk_hist<<<dim3(16, NB), 256>>>(21, 0x7FFu);
    topk_pick<<<NB, 256>>>(0, 21, 0x7FFu);
    topk_hist<<<dim3(16, NB), 256>>>(10, 0x7FFu);
    topk_pick<<<NB, 256>>>(1, 10, 0x7FFu);
    topk_hist<<<dim3(16, NB), 256>>>(0, 0x3FFu);
    topk_pick<<<NB, 256>>>(2, 0, 0x3FFu);
    topk_sum<<<dim3(16, NB), 256>>>();
    final_kernel<<<1, 32>>>(out);
}